// round 4
// baseline (speedup 1.0000x reference)
#include <cuda_runtime.h>

// x:   [N_NODES, 128] fp32 (rows 512B, 512B-aligned)
// src, dst: [E] int32 (JAX x64-disabled demotes int64 -> int32)
// out: [E] fp32
//
// Warp-per-edge with SCALAR loads: each LDG.32 has all 32 lanes reading
// consecutive floats of ONE row -> exactly one 128B sector per LDG
// (cross-LDG wavefront rate 1.0 cyc/wf, no within-LDG 2.07cyc replays).
// 8 independent single-sector loads per lane (MLP=8), 4 FMAs, then a
// 5-step butterfly reduce; lane 0 stores.

__global__ void __launch_bounds__(256) edge_dot_kernel(
    const float* __restrict__ x,
    const int* __restrict__ src,
    const int* __restrict__ dst,
    float* __restrict__ out,
    int n_edges)
{
    const int warp_id = (blockIdx.x * blockDim.x + threadIdx.x) >> 5;
    const int lane    = threadIdx.x & 31;
    if (warp_id >= n_edges) return;

    const long long s = (long long)__ldg(&src[warp_id]);
    const long long d = (long long)__ldg(&dst[warp_id]);

    const float* __restrict__ xa = x + s * 128 + lane;
    const float* __restrict__ xb = x + d * 128 + lane;

    // 8 independent loads, each exactly one 128B sector for the warp
    const float a0 = __ldg(xa +  0);
    const float a1 = __ldg(xa + 32);
    const float a2 = __ldg(xa + 64);
    const float a3 = __ldg(xa + 96);
    const float b0 = __ldg(xb +  0);
    const float b1 = __ldg(xb + 32);
    const float b2 = __ldg(xb + 64);
    const float b3 = __ldg(xb + 96);

    // two independent FMA chains, then combine
    float p0 = a0 * b0;  p0 = fmaf(a2, b2, p0);
    float p1 = a1 * b1;  p1 = fmaf(a3, b3, p1);
    float sum = p0 + p1;

    // butterfly reduce across the warp
    #pragma unroll
    for (int off = 16; off > 0; off >>= 1)
        sum += __shfl_xor_sync(0xffffffffu, sum, off);

    if (lane == 0)
        out[warp_id] = sum;
}

extern "C" void kernel_launch(void* const* d_in, const int* in_sizes, int n_in,
                              void* d_out, int out_size)
{
    const float* x   = (const float*)d_in[0];
    const int*   src = (const int*)d_in[1];
    const int*   dst = (const int*)d_in[2];
    float*       out = (float*)d_out;

    const int n_edges = in_sizes[1];            // E = 1,000,000
    const int threads = 256;                    // 8 warps/block, 8 edges/block
    const int edges_per_block = threads / 32;
    const int blocks = (n_edges + edges_per_block - 1) / edges_per_block;

    edge_dot_kernel<<<blocks, threads>>>(x, src, dst, out, n_edges);
}

// round 5
// speedup vs baseline: 1.6596x; 1.6596x over previous
#include <cuda_runtime.h>

// x:   [N_NODES, 128] fp32 (rows 512B, 512B-aligned)
// src, dst: [E] int32
// out: [E] fp32
//
// 4 edges per warp, whole warp per row, SCALAR loads:
// each LDG.32 reads 32 consecutive floats of ONE row = exactly one 128B
// sector (cross-LDG 1.0 cyc/wf; no 2.07 cyc within-LDG replays).
// 32 independent data loads per warp (high MLP), 8 FMAs/lane,
// 11-shuffle reduction for all 4 edges, coalesced 4-float store.

__global__ void __launch_bounds__(256) edge_dot_kernel(
    const float* __restrict__ x,
    const int4* __restrict__ src4,
    const int4* __restrict__ dst4,
    float* __restrict__ out,
    int n_edges)
{
    const int warp_id = (blockIdx.x * blockDim.x + threadIdx.x) >> 5;
    const int lane    = threadIdx.x & 31;
    const int base    = warp_id * 4;
    if (base >= n_edges) return;

    // broadcast index loads: one int4 per warp for src, one for dst
    const int4 s4 = __ldg(&src4[warp_id]);
    const int4 d4 = __ldg(&dst4[warp_id]);

    const float* __restrict__ a0 = x + (long long)s4.x * 128 + lane;
    const float* __restrict__ a1 = x + (long long)s4.y * 128 + lane;
    const float* __restrict__ a2 = x + (long long)s4.z * 128 + lane;
    const float* __restrict__ a3 = x + (long long)s4.w * 128 + lane;
    const float* __restrict__ b0 = x + (long long)d4.x * 128 + lane;
    const float* __restrict__ b1 = x + (long long)d4.y * 128 + lane;
    const float* __restrict__ b2 = x + (long long)d4.z * 128 + lane;
    const float* __restrict__ b3 = x + (long long)d4.w * 128 + lane;

    // 32 independent single-sector loads
    float av[4][4], bv[4][4];
    #pragma unroll
    for (int c = 0; c < 4; c++) {
        av[0][c] = __ldg(a0 + c * 32);
        av[1][c] = __ldg(a1 + c * 32);
        av[2][c] = __ldg(a2 + c * 32);
        av[3][c] = __ldg(a3 + c * 32);
        bv[0][c] = __ldg(b0 + c * 32);
        bv[1][c] = __ldg(b1 + c * 32);
        bv[2][c] = __ldg(b2 + c * 32);
        bv[3][c] = __ldg(b3 + c * 32);
    }

    float s0 = av[0][0] * bv[0][0];
    float s1 = av[1][0] * bv[1][0];
    float s2 = av[2][0] * bv[2][0];
    float s3 = av[3][0] * bv[3][0];
    #pragma unroll
    for (int c = 1; c < 4; c++) {
        s0 = fmaf(av[0][c], bv[0][c], s0);
        s1 = fmaf(av[1][c], bv[1][c], s1);
        s2 = fmaf(av[2][c], bv[2][c], s2);
        s3 = fmaf(av[3][c], bv[3][c], s3);
    }

    // reduce each edge-sum within 4-lane groups (offsets 1,2)
    s0 += __shfl_xor_sync(0xffffffffu, s0, 1);
    s1 += __shfl_xor_sync(0xffffffffu, s1, 1);
    s2 += __shfl_xor_sync(0xffffffffu, s2, 1);
    s3 += __shfl_xor_sync(0xffffffffu, s3, 1);
    s0 += __shfl_xor_sync(0xffffffffu, s0, 2);
    s1 += __shfl_xor_sync(0xffffffffu, s1, 2);
    s2 += __shfl_xor_sync(0xffffffffu, s2, 2);
    s3 += __shfl_xor_sync(0xffffffffu, s3, 2);

    // lane picks the edge (lane&3); its value is the partial of group lane>>2
    const int e = lane & 3;
    float v = (e == 0) ? s0 : (e == 1) ? s1 : (e == 2) ? s2 : s3;

    // combine the 8 groups (offsets 4,8,16)
    v += __shfl_xor_sync(0xffffffffu, v, 4);
    v += __shfl_xor_sync(0xffffffffu, v, 8);
    v += __shfl_xor_sync(0xffffffffu, v, 16);

    // lanes 0..3 hold totals for edges base..base+3 — coalesced store
    if (lane < 4 && base + lane < n_edges)
        out[base + lane] = v;
}

extern "C" void kernel_launch(void* const* d_in, const int* in_sizes, int n_in,
                              void* d_out, int out_size)
{
    const float* x    = (const float*)d_in[0];
    const int4*  src4 = (const int4*)d_in[1];
    const int4*  dst4 = (const int4*)d_in[2];
    float*       out  = (float*)d_out;

    const int n_edges = in_sizes[1];                 // E = 1,000,000 (divisible by 4)
    const int threads = 256;                         // 8 warps/block, 32 edges/block
    const int edges_per_block = (threads / 32) * 4;
    const int blocks = (n_edges + edges_per_block - 1) / edges_per_block;

    edge_dot_kernel<<<blocks, threads>>>(x, src4, dst4, out, n_edges);
}